// round 12
// baseline (speedup 1.0000x reference)
#include <cuda_runtime.h>
#include <cuda_bf16.h>
#include <math.h>

// Spiking CNN forward, B=4096.
// conv stack (f32x2 SIMT) -> Z binary bf16 -> fc1 via EXACT 3-split bf16 MMA
// -> LIF masks -> fc2 -> LIF -> softmax.

#define NB 4096
typedef unsigned long long u64;
typedef unsigned int uint32;

__device__ __nv_bfloat16 g_Zh[NB * 980];        // binary conv output (bf16 exact)
__device__ __nv_bfloat16 g_W3[3 * 128 * 992];   // Wf1 exact 3-split, [sp][n][k] zero-padded
__device__ float         g_H[NB * 128];         // fc1 output

// ---- packed f32x2 helpers ----
__device__ __forceinline__ u64 splat2(float a){
    u64 r; asm("mov.b64 %0, {%1, %1};" : "=l"(r) : "f"(a)); return r;
}
__device__ __forceinline__ u64 pack2(float a, float b){
    u64 r; asm("mov.b64 %0, {%1, %2};" : "=l"(r) : "f"(a), "f"(b)); return r;
}
__device__ __forceinline__ void unpack2(u64 v, float &x, float &y){
    asm("mov.b64 {%0, %1}, %2;" : "=f"(x), "=f"(y) : "l"(v));
}
__device__ __forceinline__ u64 fma2(u64 a, u64 b, u64 c){
    u64 d; asm("fma.rn.f32x2 %0, %1, %2, %3;" : "=l"(d) : "l"(a), "l"(b), "l"(c));
    return d;
}

__device__ __forceinline__ void mma16816(float d[4], const uint32 a[4], const uint32 b[2]){
    asm("mma.sync.aligned.m16n8k16.row.col.f32.bf16.bf16.f32 "
        "{%0,%1,%2,%3}, {%4,%5,%6,%7}, {%8,%9}, {%0,%1,%2,%3};"
        : "+f"(d[0]), "+f"(d[1]), "+f"(d[2]), "+f"(d[3])
        : "r"(a[0]), "r"(a[1]), "r"(a[2]), "r"(a[3]), "r"(b[0]), "r"(b[1]));
}

// ===========================================================================
// kW: exact 3-way bf16 split of Wf1 into g_W3[sp][n][k], zero-padded.
// ===========================================================================
__global__ void __launch_bounds__(256)
kW(const float* __restrict__ Wf1)
{
    int idx = blockIdx.x * 256 + threadIdx.x;   // over 128*992
    if (idx < 128 * 992) {
        int n = idx / 992, k = idx - n * 992;
        float w = (n < 100 && k < 980) ? Wf1[n * 980 + k] : 0.f;
        __nv_bfloat16 b1 = __float2bfloat16(w);
        float r1 = w - __bfloat162float(b1);
        __nv_bfloat16 b2 = __float2bfloat16(r1);
        float r2 = r1 - __bfloat162float(b2);
        __nv_bfloat16 b3 = __float2bfloat16(r2);
        g_W3[idx]              = b1;
        g_W3[128 * 992 + idx]  = b2;
        g_W3[2 * 128 * 992 + idx] = b3;
    }
}

// ===========================================================================
// K1: fused conv stack (R8/R10 compute; epilogue stores bf16 Z)
// ===========================================================================
#define K1_SMEM 58280

__global__ void __launch_bounds__(160)
k1_conv(const float* __restrict__ x, const float* __restrict__ Wc1,
        const float* __restrict__ Wc2)
{
    extern __shared__ char smraw[];
    float* xs  = (float*)(smraw);            // [2][30][30]
    u64*   w1p = (u64*)  (smraw + 7200);     // [5 ocp][9]
    u64*   w2p = (u64*)  (smraw + 7560);     // [10 ocp][90]
    float* p1s = (float*)(smraw + 14760);    // [2][10][16][34]

    const int tid = threadIdx.x;
    const int s0  = blockIdx.x * 2;
    const __nv_bfloat16 ONE  = __float2bfloat16(1.0f);
    const __nv_bfloat16 ZERO = __float2bfloat16(0.0f);

    for (int i = tid; i < 1800; i += 160) {
        int sp = i / 900, e = i - sp * 900;
        int r = e / 30, c = e - r * 30;
        float v = 0.f;
        if (r >= 1 && r <= 28 && c >= 1 && c <= 28)
            v = x[(s0 + sp) * 784 + (r - 1) * 28 + (c - 1)];
        xs[i] = v;
    }
    if (tid < 45) {
        int cp = tid / 9, k = tid - cp * 9;
        w1p[tid] = pack2(Wc1[(2 * cp) * 9 + k], Wc1[(2 * cp + 1) * 9 + k]);
    }
    for (int i = tid; i < 900; i += 160) {
        int ocp = i / 90, t = i - ocp * 90;
        w2p[i] = pack2(Wc2[(2 * ocp) * 90 + t], Wc2[(2 * ocp + 1) * 90 + t]);
    }
    for (int i = tid; i < 10880; i += 160) p1s[i] = 0.f;
    __syncthreads();

    for (int task = tid; task < 1960; task += 160) {
        int sp  = task / 980;
        int r   = task - sp * 980;
        int cp  = r / 196;
        int pos = r - cp * 196;
        int py = pos / 14, px = pos - py * 14;
        const float* xb = xs + sp * 900 + (2 * py) * 30 + 2 * px;
        u64 acc[2][2];
        acc[0][0] = acc[0][1] = acc[1][0] = acc[1][1] = 0ull;
        #pragma unroll
        for (int rr = 0; rr < 4; rr++) {
            u64 cc[4];
            #pragma unroll
            for (int c = 0; c < 4; c++) cc[c] = splat2(xb[rr * 30 + c]);
            #pragma unroll
            for (int dy = 0; dy < 2; dy++) {
                int ky = rr - dy;
                if (ky >= 0 && ky <= 2) {
                    #pragma unroll
                    for (int kx = 0; kx < 3; kx++) {
                        u64 w = w1p[cp * 9 + ky * 3 + kx];
                        acc[dy][0] = fma2(cc[kx],     w, acc[dy][0]);
                        acc[dy][1] = fma2(cc[kx + 1], w, acc[dy][1]);
                    }
                }
            }
        }
        float f0 = 0.f, f1 = 0.f, lo, hi;
        #pragma unroll
        for (int dy = 0; dy < 2; dy++)
            #pragma unroll
            for (int dx = 0; dx < 2; dx++) {
                unpack2(acc[dy][dx], lo, hi);
                if (lo >= 1.f) f0 = 1.f;
                if (hi >= 1.f) f1 = 1.f;
            }
        int base = ((sp * 10 + 2 * cp) * 16 + (py + 1)) * 34 + 2 * (px + 1);
        p1s[base]       = f0; p1s[base + 1]   = f0;
        p1s[base + 544] = f1; p1s[base + 545] = f1;
    }
    __syncthreads();

    if (tid < 140) {
        int sp  = tid / 70;
        int r70 = tid - sp * 70;
        int ocp = r70 / 7, py = r70 - ocp * 7;
        u64 acc[2][14];
        #pragma unroll
        for (int i = 0; i < 2; i++)
            #pragma unroll
            for (int j = 0; j < 14; j++) acc[i][j] = 0ull;

        const float* pbase = p1s + sp * 5440 + (2 * py) * 34;
        const u64*   wq    = w2p + ocp * 90;

        for (int ic = 0; ic < 10; ic++) {
            u64 w[9];
            #pragma unroll
            for (int k = 0; k < 9; k++) w[k] = wq[ic * 9 + k];
            const float* prow = pbase + ic * 544;
            #pragma unroll
            for (int rr = 0; rr < 4; rr++) {
                u64 arow[16];
                #pragma unroll
                for (int c = 0; c < 16; c++)
                    arow[c] = *(const u64*)(prow + rr * 34 + 2 * c);
                #pragma unroll
                for (int pr = 0; pr < 2; pr++) {
                    int ky = rr - pr;
                    if (ky >= 0 && ky <= 2) {
                        #pragma unroll
                        for (int kx = 0; kx < 3; kx++) {
                            u64 wv = w[ky * 3 + kx];
                            #pragma unroll
                            for (int ox = 0; ox < 14; ox++)
                                acc[pr][ox] = fma2(arow[ox + kx], wv, acc[pr][ox]);
                        }
                    }
                }
            }
        }
        int s = s0 + sp;
        __nv_bfloat16* z0 = g_Zh + s * 980 + (2 * ocp) * 49 + py * 7;
        #pragma unroll
        for (int px = 0; px < 7; px++) {
            float a, b, c, d, e, f, g, h;
            unpack2(acc[0][2 * px],     a, b);
            unpack2(acc[0][2 * px + 1], c, d);
            unpack2(acc[1][2 * px],     e, f);
            unpack2(acc[1][2 * px + 1], g, h);
            z0[px]      = (a >= 1.f || c >= 1.f || e >= 1.f || g >= 1.f) ? ONE : ZERO;
            z0[49 + px] = (b >= 1.f || d >= 1.f || f >= 1.f || h >= 1.f) ? ONE : ZERO;
        }
    }
}

// ===========================================================================
// K2: H = Z @ Wf1^T via exact 3-split bf16 MMA (m16n8k16).
// Block 512 thr = 16 warps (4m x 4n) covering 64m x 32n. Grid (64, 4).
// K loop: 62 chunks of 16. A-frags reused across the 3 weight splits.
// ===========================================================================
__global__ void __launch_bounds__(512)
k2_mma()
{
    __shared__ uint32 Zs[64 * 8];        // [m][q], q = pair-of-bf16 index (16 k = 8 u32)
    __shared__ uint32 Ws[3 * 32 * 8];    // [sp][n][q]

    const int tid  = threadIdx.x;
    const int warp = tid >> 5, lane = tid & 31;
    const int wm = warp >> 2, wn = warp & 3;
    const int g  = lane >> 2, t = lane & 3;
    const int m0  = blockIdx.x * 64;
    const int gn0 = blockIdx.y * 32;

    float d[4] = {0.f, 0.f, 0.f, 0.f};

    const int zm = tid >> 3, zq = tid & 7;   // staging coords for Z

    for (int c = 0; c < 62; c++) {
        int kc = c * 16;
        __syncthreads();
        // stage Z: one u32 (2 bf16) per thread
        {
            int k = kc + 2 * zq;
            uint32 v = 0u;
            if (k < 980)
                v = *(const uint32*)(g_Zh + (m0 + zm) * 980 + k);
            Zs[zm * 8 + zq] = v;
        }
        // stage W: 768 u32
        for (int e = tid; e < 768; e += 512) {
            int sp = e >> 8, r = e & 255, n = r >> 3, q = r & 7;
            Ws[e] = *(const uint32*)(g_W3 + sp * (128 * 992) + (gn0 + n) * 992 + kc + 2 * q);
        }
        __syncthreads();

        uint32 a[4];
        const uint32* zr = Zs + (wm * 16) * 8;
        a[0] = zr[g * 8 + t];              // A[g][2t,2t+1]
        a[1] = zr[(g + 8) * 8 + t];        // A[g+8][2t,2t+1]
        a[2] = zr[g * 8 + t + 4];          // A[g][2t+8,2t+9]
        a[3] = zr[(g + 8) * 8 + t + 4];    // A[g+8][2t+8,2t+9]

        #pragma unroll
        for (int sp = 0; sp < 3; sp++) {
            uint32 b[2];
            const uint32* wr = Ws + sp * 256 + (wn * 8) * 8;
            b[0] = wr[g * 8 + t];          // B[2t,2t+1][n=g]
            b[1] = wr[g * 8 + t + 4];      // B[2t+8,2t+9][n=g]
            mma16816(d, a, b);
        }
    }

    int m = m0 + wm * 16 + g;
    int n = gn0 + wn * 8 + 2 * t;
    g_H[m * 128 + n]           = d[0];
    g_H[m * 128 + n + 1]       = d[1];
    g_H[(m + 8) * 128 + n]     = d[2];
    g_H[(m + 8) * 128 + n + 1] = d[3];
}

// ===========================================================================
// K3: one warp per sample. grid 512, block 256 (8 warps = 8 samples).
// ===========================================================================
__device__ __forceinline__ uint32 lifmask(float h){
    float v = 0.f; uint32 m = 0u;
    #pragma unroll
    for (int t = 0; t < 32; t++) {
        v += (h - v) * 0.5f;
        if (v >= 1.f) { m |= (1u << t); v = 0.f; }
    }
    return m;
}

__global__ void __launch_bounds__(256)
k3_lif(const float* __restrict__ Wf2, float* __restrict__ out)
{
    __shared__ u64    W2p[500];          // i-pairs: (Wf2[2p][j], Wf2[2p+1][j])
    __shared__ uint32 Msk[8 * 100];
    __shared__ float  ysm[8 * 320];
    __shared__ float  cs[8 * 16];

    const int tid  = threadIdx.x;
    const int wid  = tid >> 5, lane = tid & 31;
    const int m    = blockIdx.x * 8 + wid;

    for (int e = tid; e < 500; e += 256) {
        int p = e / 100, j = e - p * 100;
        W2p[e] = pack2(Wf2[(2 * p) * 100 + j], Wf2[(2 * p + 1) * 100 + j]);
    }
    __syncthreads();

    // Phase A+B: LIF-1 masks from g_H
    #pragma unroll
    for (int q = 0; q < 4; q++) {
        int n = q * 32 + lane;
        if (n < 100)
            Msk[wid * 100 + n] = lifmask(g_H[m * 128 + n]);
    }
    __syncwarp();

    // Phase C: lane = timestep t; y[i] via i-paired fma2
    {
        u64 y[5];
        #pragma unroll
        for (int p = 0; p < 5; p++) y[p] = 0ull;
        const uint32* mk = Msk + wid * 100;
        #pragma unroll 4
        for (int j = 0; j < 100; j++) {
            u64 b = splat2((float)((mk[j] >> lane) & 1u));
            #pragma unroll
            for (int p = 0; p < 5; p++)
                y[p] = fma2(b, W2p[p * 100 + j], y[p]);
        }
        float* yr = ysm + wid * 320 + lane * 10;
        #pragma unroll
        for (int p = 0; p < 5; p++) {
            float a, bb; unpack2(y[p], a, bb);
            yr[2 * p] = a; yr[2 * p + 1] = bb;
        }
    }
    __syncwarp();

    // Phase D: v2 LIF + softmax
    if (lane < 10) {
        float v = 0.f, cnt = 0.f;
        const float* yr = ysm + wid * 320;
        #pragma unroll
        for (int t = 0; t < 32; t++) {
            float yv = yr[t * 10 + lane];
            v += (yv - v) * 0.5f;
            if (v >= 1.f) { cnt += 1.f; v = 0.f; }
        }
        cs[wid * 16 + lane] = cnt * (1.f / 32.f);
    }
    __syncwarp();
    if (lane < 10) {
        const float* c = cs + wid * 16;
        float mx = -1e30f;
        #pragma unroll
        for (int q = 0; q < 10; q++) mx = fmaxf(mx, c[q]);
        float sum = 0.f;
        #pragma unroll
        for (int q = 0; q < 10; q++) sum += expf(c[q] - mx);
        out[m * 10 + lane] = expf(c[lane] - mx) / sum;
    }
}

// ===========================================================================
extern "C" void kernel_launch(void* const* d_in, const int* in_sizes, int n_in,
                              void* d_out, int out_size)
{
    const float* x   = (const float*)d_in[0];
    const float* Wc1 = (const float*)d_in[1];
    const float* Wc2 = (const float*)d_in[2];
    const float* Wf1 = (const float*)d_in[3];
    const float* Wf2 = (const float*)d_in[4];
    float* out = (float*)d_out;

    cudaFuncSetAttribute(k1_conv, cudaFuncAttributeMaxDynamicSharedMemorySize, K1_SMEM);

    kW<<<(128 * 992 + 255) / 256, 256>>>(Wf1);
    k1_conv<<<NB / 2, 160, K1_SMEM>>>(x, Wc1, Wc2);
    dim3 g2(64, 4);
    k2_mma<<<g2, 512>>>();
    k3_lif<<<NB / 8, 256>>>(Wf2, out);
}